// round 1
// baseline (speedup 1.0000x reference)
#include <cuda_runtime.h>
#include <math.h>

#define BATCH 8
#define TT 96
#define NNODE 200
#define EMB 32
#define HID 32
#define HOR 24
#define FV 400
#define NSEQ (BATCH*NNODE)   /* 1600 */
#define ROWS (BATCH*TT)      /* 768  */
#define HMT 6400

// ---- scratch (static device globals; no allocations allowed) ----
__device__ float g_q[ROWS*EMB];
__device__ float g_k[ROWS*EMB];
__device__ float g_E[ROWS*TT];
__device__ float g_att[ROWS*FV];
__device__ float g_Y[ROWS*HMT];          // ~19.6 MB
__device__ float g_GI[TT*NSEQ*96];       // ~59 MB

__device__ __forceinline__ float sigf(float x){ return 1.0f/(1.0f + __expf(-x)); }

// ---------------------------------------------------------------------------
// K0: time embedding + q/k projections.  grid=768 (one per (b,t)), 32 threads.
// ---------------------------------------------------------------------------
__global__ void k0_qk(const float* __restrict__ ts, const float* __restrict__ te_w,
                      const float* __restrict__ te_b, const float* __restrict__ q_w,
                      const float* __restrict__ q_b, const float* __restrict__ k_w){
    int row = blockIdx.x; int e = threadIdx.x;
    __shared__ float te[EMB];
    float v = ts[row]*te_w[e] + te_b[e];
    if (e > 0) v = sinf(v);
    te[e] = v; __syncthreads();
    float q = q_b[e], k = 0.f;
    #pragma unroll
    for (int i=0;i<EMB;i++){
        q = fmaf(te[i], q_w[e*EMB+i], q);
        k = fmaf(te[i], k_w[e*EMB+i], k);
    }
    g_q[row*EMB+e] = q;
    g_k[row*EMB+e] = k;
}

// ---------------------------------------------------------------------------
// K1: scores + row max + E=exp(s-M).  grid=768 (b,q), 96 threads (one per k).
// ---------------------------------------------------------------------------
__global__ void k1_scores(){
    int row = blockIdx.x; int b = row/TT; int tid = threadIdx.x;
    __shared__ float qv[EMB];
    __shared__ float ks[TT*33];      // pad 33 to avoid bank conflicts
    __shared__ float sbuf[TT];
    __shared__ float smax;
    if (tid < EMB) qv[tid] = g_q[row*EMB + tid];
    for (int idx = tid; idx < TT*EMB; idx += 96){
        int kk = idx >> 5, i = idx & 31;
        ks[kk*33 + i] = g_k[(b*TT + kk)*EMB + i];
    }
    __syncthreads();
    float s = 0.f;
    #pragma unroll
    for (int i=0;i<EMB;i++) s = fmaf(qv[i], ks[tid*33+i], s);
    s *= 0.17677669529663687f;   // 1/sqrt(32)
    sbuf[tid] = s; __syncthreads();
    if (tid < 32){
        float m = fmaxf(sbuf[tid], fmaxf(sbuf[tid+32], sbuf[tid+64]));
        #pragma unroll
        for (int o=16;o;o>>=1) m = fmaxf(m, __shfl_xor_sync(0xffffffffu, m, o));
        if (tid==0) smax = m;
    }
    __syncthreads();
    g_E[row*TT + tid] = __expf(s - smax);
}

// ---------------------------------------------------------------------------
// K2: masked softmax-weighted aggregation.  grid=768 (b,q), 256 thr (n<200).
// out_att[.,2n] = sum_k E*m*x / sum_k E*m ; out_att[.,2n+1] = 1 (D>0),
// with exact uniform fallback when all k masked for (b,n).
// ---------------------------------------------------------------------------
__global__ void k2_att(const float* __restrict__ x, const float* __restrict__ mask){
    int row = blockIdx.x; int b = row/TT;
    int tid = threadIdx.x;
    __shared__ float Es[TT];
    if (tid < TT) Es[tid] = g_E[row*TT + tid];
    __syncthreads();
    if (tid < NNODE){
        int n = tid;
        float num=0.f, den=0.f, sx=0.f;
        const float* xb = x    + b*TT*NNODE + n;
        const float* mb = mask + b*TT*NNODE + n;
        #pragma unroll 4
        for (int k=0;k<TT;k++){
            float e  = Es[k];
            float xv = xb[k*NNODE];
            float mv = mb[k*NNODE];
            float em = e*mv;
            den += em;
            num = fmaf(em, xv, num);
            sx += xv;
        }
        float oe, oo;
        if (den > 0.f){ oe = num/den; oo = 1.f; }
        else          { oe = sx*(1.0f/96.0f); oo = 0.f; }
        g_att[row*FV + 2*n]   = oe;
        g_att[row*FV + 2*n+1] = oo;
    }
}

// ---------------------------------------------------------------------------
// K3: V projection GEMM (NT): Y[768x6400] = att[768x400] * v_w[6400x400]^T + v_b
// Tiled fp32 SGEMM: 64x64x16 tiles, 256 threads, 4x4 per thread.
// ---------------------------------------------------------------------------
#define BM 64
#define BN 64
#define BK 16
__global__ void k3_vgemm(const float* __restrict__ vw, const float* __restrict__ vb){
    __shared__ float As[BK][BM];
    __shared__ float Bs[BK][BN];
    int tid = threadIdx.x;
    int tx = tid & 15, ty = tid >> 4;
    int bm = blockIdx.y, bn = blockIdx.x;
    const float* Ab = g_att + bm*BM*FV;
    const float* Bb = vw    + bn*BN*FV;
    int lr = tid >> 2;            // 0..63
    int lc = (tid & 3) << 2;      // 0,4,8,12
    float acc[4][4];
    #pragma unroll
    for (int i=0;i<4;i++)
        #pragma unroll
        for (int j=0;j<4;j++) acc[i][j]=0.f;

    for (int k0=0;k0<FV;k0+=BK){
        float4 av = *(const float4*)(Ab + lr*FV + k0 + lc);
        float4 bv = *(const float4*)(Bb + lr*FV + k0 + lc);
        As[lc+0][lr]=av.x; As[lc+1][lr]=av.y; As[lc+2][lr]=av.z; As[lc+3][lr]=av.w;
        Bs[lc+0][lr]=bv.x; Bs[lc+1][lr]=bv.y; Bs[lc+2][lr]=bv.z; Bs[lc+3][lr]=bv.w;
        __syncthreads();
        #pragma unroll
        for (int kk=0;kk<BK;kk++){
            float4 a4 = *(const float4*)&As[kk][ty*4];
            float4 b4 = *(const float4*)&Bs[kk][tx*4];
            acc[0][0]=fmaf(a4.x,b4.x,acc[0][0]); acc[0][1]=fmaf(a4.x,b4.y,acc[0][1]);
            acc[0][2]=fmaf(a4.x,b4.z,acc[0][2]); acc[0][3]=fmaf(a4.x,b4.w,acc[0][3]);
            acc[1][0]=fmaf(a4.y,b4.x,acc[1][0]); acc[1][1]=fmaf(a4.y,b4.y,acc[1][1]);
            acc[1][2]=fmaf(a4.y,b4.z,acc[1][2]); acc[1][3]=fmaf(a4.y,b4.w,acc[1][3]);
            acc[2][0]=fmaf(a4.z,b4.x,acc[2][0]); acc[2][1]=fmaf(a4.z,b4.y,acc[2][1]);
            acc[2][2]=fmaf(a4.z,b4.z,acc[2][2]); acc[2][3]=fmaf(a4.z,b4.w,acc[2][3]);
            acc[3][0]=fmaf(a4.w,b4.x,acc[3][0]); acc[3][1]=fmaf(a4.w,b4.y,acc[3][1]);
            acc[3][2]=fmaf(a4.w,b4.z,acc[3][2]); acc[3][3]=fmaf(a4.w,b4.w,acc[3][3]);
        }
        __syncthreads();
    }
    int row0 = bm*BM + ty*4;
    int col0 = bn*BN + tx*4;
    float4 bb = *(const float4*)(vb + col0);
    #pragma unroll
    for (int i=0;i<4;i++){
        float4 o;
        o.x = acc[i][0]+bb.x; o.y = acc[i][1]+bb.y;
        o.z = acc[i][2]+bb.z; o.w = acc[i][3]+bb.w;
        *(float4*)(g_Y + (row0+i)*HMT + col0) = o;
    }
}

// ---------------------------------------------------------------------------
// K4: GRU input GEMM: GI[t,s,g] = Y[b,t,n,:] . wih[g,:] + bih[g]
// grid = 96*50 blocks (t, 32-seq chunk), 192 threads (96 gates x 2 halves).
// ---------------------------------------------------------------------------
__global__ void k4_gi(const float* __restrict__ wih, const float* __restrict__ bih){
    int t  = blockIdx.x / 50;
    int s0 = (blockIdx.x % 50) * 32;
    int tid = threadIdx.x;
    __shared__ __align__(16) float xsh[32*32];
    for (int idx = tid; idx < 1024; idx += 192){
        int sL = idx >> 5, i = idx & 31;
        int s = s0 + sL;
        int b = s / NNODE, n = s % NNODE;
        xsh[idx] = g_Y[((b*TT + t)*NNODE + n)*HID + i];
    }
    __syncthreads();
    int g = tid % 96;
    int half = tid / 96;
    float4 w4[8];
    #pragma unroll
    for (int i4=0;i4<8;i4++) w4[i4] = *(const float4*)(wih + g*32 + i4*4);
    float bg = bih[g];
    for (int sL = half*16; sL < half*16+16; sL++){
        const float4* xr = (const float4*)&xsh[sL*32];
        float acc = bg;
        #pragma unroll
        for (int i4=0;i4<8;i4++){
            float4 xv = xr[i4];
            acc = fmaf(w4[i4].x, xv.x, acc);
            acc = fmaf(w4[i4].y, xv.y, acc);
            acc = fmaf(w4[i4].z, xv.z, acc);
            acc = fmaf(w4[i4].w, xv.w, acc);
        }
        g_GI[(t*NSEQ + s0 + sL)*96 + g] = acc;
    }
}

// ---------------------------------------------------------------------------
// K5: GRU recurrence (warp = one sequence, h one element per lane) + fused MLP.
// grid = 200 blocks x 256 threads (8 warps = 8 sequences each).
// ---------------------------------------------------------------------------
__global__ void __launch_bounds__(256)
k5_gru(const float* __restrict__ whh, const float* __restrict__ bhh,
       const float* __restrict__ mlp_w, const float* __restrict__ mlp_b,
       const float* __restrict__ out_w, const float* __restrict__ out_b,
       float* __restrict__ out){
    int wid = threadIdx.x >> 5;
    int j   = threadIdx.x & 31;
    int seq = blockIdx.x*8 + wid;
    int b = seq / NNODE, n = seq % NNODE;

    float wr[32], wz[32], wn[32];
    #pragma unroll
    for (int i=0;i<32;i++){
        wr[i] = whh[j*32+i];
        wz[i] = whh[(32+j)*32+i];
        wn[i] = whh[(64+j)*32+i];
    }
    float bhr = bhh[j], bhz = bhh[32+j], bhn = bhh[64+j];
    const float* gi = g_GI + seq*96;

    float h = 0.f;
    for (int t=0;t<TT;t++){
        float hr=0.f, hz=0.f, hn=0.f;
        #pragma unroll
        for (int i=0;i<32;i++){
            float hv = __shfl_sync(0xffffffffu, h, i);
            hr = fmaf(wr[i], hv, hr);
            hz = fmaf(wz[i], hv, hz);
            hn = fmaf(wn[i], hv, hn);
        }
        const float* gt = gi + (size_t)t*(NSEQ*96);
        float r  = sigf(gt[j]    + hr + bhr);
        float z  = sigf(gt[32+j] + hz + bhz);
        float nn = tanhf(gt[64+j] + r*(hn + bhn));
        h = (1.f - z)*nn + z*h;
    }

    // MLP: h2 = relu(h @ mlp_w^T + mlp_b); y = h2 @ out_w^T + out_b
    float h2 = mlp_b[j];
    #pragma unroll
    for (int i=0;i<32;i++)
        h2 = fmaf(mlp_w[j*32+i], __shfl_sync(0xffffffffu, h, i), h2);
    h2 = fmaxf(h2, 0.f);

    float y = (j < HOR) ? out_b[j] : 0.f;
    #pragma unroll
    for (int i=0;i<32;i++){
        float v = __shfl_sync(0xffffffffu, h2, i);
        if (j < HOR) y = fmaf(out_w[j*32+i], v, y);
    }
    if (j < HOR) out[(b*HOR + j)*NNODE + n] = y;
}

// ---------------------------------------------------------------------------
extern "C" void kernel_launch(void* const* d_in, const int* in_sizes, int n_in,
                              void* d_out, int out_size){
    const float* x    = (const float*)d_in[0];
    // d_in[1] = u (unused by the model)
    const float* mask = (const float*)d_in[2];
    const float* ts   = (const float*)d_in[3];
    const float* te_w = (const float*)d_in[4];
    const float* te_b = (const float*)d_in[5];
    const float* q_w  = (const float*)d_in[6];
    const float* q_b  = (const float*)d_in[7];
    const float* k_w  = (const float*)d_in[8];
    const float* v_w  = (const float*)d_in[9];
    const float* v_b  = (const float*)d_in[10];
    const float* wih  = (const float*)d_in[11];
    const float* whh  = (const float*)d_in[12];
    const float* bih  = (const float*)d_in[13];
    const float* bhh  = (const float*)d_in[14];
    const float* mlpw = (const float*)d_in[15];
    const float* mlpb = (const float*)d_in[16];
    const float* outw = (const float*)d_in[17];
    const float* outb = (const float*)d_in[18];
    float* out = (float*)d_out;

    k0_qk<<<ROWS, 32>>>(ts, te_w, te_b, q_w, q_b, k_w);
    k1_scores<<<ROWS, 96>>>();
    k2_att<<<ROWS, 256>>>(x, mask);
    k3_vgemm<<<dim3(HMT/BN, ROWS/BM), 256>>>(v_w, v_b);
    k4_gi<<<TT*50, 192>>>(wih, bih);
    k5_gru<<<NSEQ/8, 256>>>(whh, bhh, mlpw, mlpb, outw, outb, out);
}

// round 2
// speedup vs baseline: 1.2496x; 1.2496x over previous
#include <cuda_runtime.h>
#include <math.h>

#define BATCH 8
#define TT 96
#define NNODE 200
#define EMB 32
#define HID 32
#define HOR 24
#define FV 400
#define KEV 200              /* even-column K dim */
#define NSEQ (BATCH*NNODE)   /* 1600 */
#define ROWS (BATCH*TT)      /* 768  */
#define HMT 6400

// ---- scratch (static device globals; no allocations allowed) ----
__device__ float g_q[ROWS*EMB];
__device__ float g_k[ROWS*EMB];
__device__ float g_E[ROWS*TT];
__device__ float g_att_e[ROWS*KEV];      // even (data) attention outputs
__device__ unsigned g_zmask[ROWS][7];    // per-row bitmask of all-masked nodes
__device__ unsigned g_zany[ROWS];
__device__ float g_vwe[HMT*KEV];         // packed even columns of v_w (5.1 MB)
__device__ float g_colsum[HMT];          // vb + sum of odd v_w columns
__device__ float g_Y[ROWS*HMT];          // ~19.6 MB
__device__ float g_GI[TT*NSEQ*96];       // ~59 MB

__device__ __forceinline__ float sigf(float x){ return 1.0f/(1.0f + __expf(-x)); }
__device__ __forceinline__ float ftanh(float x){ return 2.0f*sigf(2.0f*x) - 1.0f; }

// ---------------------------------------------------------------------------
// K0: time embedding + q/k projections.  grid=768, 32 threads.
// ---------------------------------------------------------------------------
__global__ void k0_qk(const float* __restrict__ ts, const float* __restrict__ te_w,
                      const float* __restrict__ te_b, const float* __restrict__ q_w,
                      const float* __restrict__ q_b, const float* __restrict__ k_w){
    int row = blockIdx.x; int e = threadIdx.x;
    __shared__ float te[EMB];
    float v = ts[row]*te_w[e] + te_b[e];
    if (e > 0) v = sinf(v);
    te[e] = v; __syncthreads();
    float q = q_b[e], k = 0.f;
    #pragma unroll
    for (int i=0;i<EMB;i++){
        q = fmaf(te[i], q_w[e*EMB+i], q);
        k = fmaf(te[i], k_w[e*EMB+i], k);
    }
    g_q[row*EMB+e] = q;
    g_k[row*EMB+e] = k;
}

// ---------------------------------------------------------------------------
// K1: scores + row max + E=exp(s-M).  grid=768, 96 threads.
// ---------------------------------------------------------------------------
__global__ void k1_scores(){
    int row = blockIdx.x; int b = row/TT; int tid = threadIdx.x;
    __shared__ float qv[EMB];
    __shared__ float ks[TT*33];
    __shared__ float sbuf[TT];
    __shared__ float smax;
    if (tid < EMB) qv[tid] = g_q[row*EMB + tid];
    for (int idx = tid; idx < TT*EMB; idx += 96){
        int kk = idx >> 5, i = idx & 31;
        ks[kk*33 + i] = g_k[(b*TT + kk)*EMB + i];
    }
    __syncthreads();
    float s = 0.f;
    #pragma unroll
    for (int i=0;i<EMB;i++) s = fmaf(qv[i], ks[tid*33+i], s);
    s *= 0.17677669529663687f;
    sbuf[tid] = s; __syncthreads();
    if (tid < 32){
        float m = fmaxf(sbuf[tid], fmaxf(sbuf[tid+32], sbuf[tid+64]));
        #pragma unroll
        for (int o=16;o;o>>=1) m = fmaxf(m, __shfl_xor_sync(0xffffffffu, m, o));
        if (tid==0) smax = m;
    }
    __syncthreads();
    g_E[row*TT + tid] = __expf(s - smax);
}

// ---------------------------------------------------------------------------
// K2: masked softmax aggregation -> even outputs + zero-node bitmask.
// grid=768 (b,q), 256 threads (n<200 active).
// ---------------------------------------------------------------------------
__global__ void k2_att(const float* __restrict__ x, const float* __restrict__ mask){
    int row = blockIdx.x; int b = row/TT;
    int tid = threadIdx.x;
    __shared__ float Es[TT];
    __shared__ unsigned zm[7];
    __shared__ unsigned zany;
    if (tid < TT) Es[tid] = g_E[row*TT + tid];
    if (tid < 7) zm[tid] = 0u;
    if (tid == 7+32) zany = 0u;
    __syncthreads();
    if (tid < NNODE){
        int n = tid;
        float num=0.f, den=0.f, sx=0.f;
        const float* xb = x    + b*TT*NNODE + n;
        const float* mb = mask + b*TT*NNODE + n;
        #pragma unroll 4
        for (int k=0;k<TT;k++){
            float e  = Es[k];
            float xv = xb[k*NNODE];
            float mv = mb[k*NNODE];
            float em = e*mv;
            den += em;
            num = fmaf(em, xv, num);
            sx += xv;
        }
        float oe;
        if (den > 0.f){ oe = num/den; }
        else {
            oe = sx*(1.0f/96.0f);
            atomicOr(&zm[n>>5], 1u<<(n&31));
            atomicOr(&zany, 1u);
        }
        g_att_e[row*KEV + n] = oe;
    }
    __syncthreads();
    if (tid < 7) g_zmask[row][tid] = zm[tid];
    if (tid == 7+32) g_zany[row] = zany;
}

// ---------------------------------------------------------------------------
// K2b: pack even columns of v_w, and colsum = vb + sum(odd columns).
// one warp per output row j; grid=800 x 256.
// ---------------------------------------------------------------------------
__global__ void k2b_pack(const float* __restrict__ vw, const float* __restrict__ vb){
    int j = (blockIdx.x*256 + threadIdx.x) >> 5;
    int lane = threadIdx.x & 31;
    const float4* src = (const float4*)(vw + (size_t)j*FV);
    float os = 0.f;
    #pragma unroll
    for (int c=lane; c<100; c+=32){
        float4 v = src[c];                    // cols 4c..4c+3
        *(float2*)&g_vwe[(size_t)j*KEV + 2*c] = make_float2(v.x, v.z);
        os += v.y + v.w;
    }
    #pragma unroll
    for (int o=16;o;o>>=1) os += __shfl_xor_sync(0xffffffffu, os, o);
    if (lane == 0) g_colsum[j] = vb[j] + os;
}

// ---------------------------------------------------------------------------
// K3: Y[768x6400] = att_e[768x200] @ vwe[6400x200]^T + colsum (+rare corr.)
// 128x128x8 double-buffered SGEMM, 256 threads, 8x8 per thread.
// ---------------------------------------------------------------------------
__global__ void __launch_bounds__(256,2)
k3_vgemm(const float* __restrict__ vw){
    __shared__ float As[2][8][128];
    __shared__ float Bs[2][8][128];
    int tid = threadIdx.x;
    int bn = blockIdx.x, bm = blockIdx.y;
    int warp = tid>>5, lane = tid&31;
    int tm = (warp>>1)*32 + ((lane>>3)<<2);   // 0..124
    int tn = (warp&1)*64  + ((lane&7)<<2);    // 0..92

    int lrow = tid>>1;            // 0..127
    int lk   = (tid&1)<<2;        // 0 or 4

    const float* Ag = g_att_e + (size_t)(bm*128 + lrow)*KEV + lk;
    const float* Bg = g_vwe   + (size_t)(bn*128 + lrow)*KEV + lk;

    float4 a_st = *(const float4*)Ag;
    float4 b_st = *(const float4*)Bg;
    As[0][lk+0][lrow]=a_st.x; As[0][lk+1][lrow]=a_st.y;
    As[0][lk+2][lrow]=a_st.z; As[0][lk+3][lrow]=a_st.w;
    Bs[0][lk+0][lrow]=b_st.x; Bs[0][lk+1][lrow]=b_st.y;
    Bs[0][lk+2][lrow]=b_st.z; Bs[0][lk+3][lrow]=b_st.w;
    __syncthreads();

    float acc[8][8];
    #pragma unroll
    for (int i=0;i<8;i++)
        #pragma unroll
        for (int j=0;j<8;j++) acc[i][j]=0.f;

    int cur = 0;
    #pragma unroll 1
    for (int it=0; it<25; ++it){
        if (it < 24){
            a_st = *(const float4*)(Ag + (it+1)*8);
            b_st = *(const float4*)(Bg + (it+1)*8);
        }
        #pragma unroll
        for (int k=0;k<8;k++){
            float4 a0 = *(const float4*)&As[cur][k][tm];
            float4 a1 = *(const float4*)&As[cur][k][tm+16];
            float4 b0 = *(const float4*)&Bs[cur][k][tn];
            float4 b1 = *(const float4*)&Bs[cur][k][tn+32];
            float ar[8] = {a0.x,a0.y,a0.z,a0.w,a1.x,a1.y,a1.z,a1.w};
            float br[8] = {b0.x,b0.y,b0.z,b0.w,b1.x,b1.y,b1.z,b1.w};
            #pragma unroll
            for (int i=0;i<8;i++)
                #pragma unroll
                for (int j=0;j<8;j++)
                    acc[i][j] = fmaf(ar[i], br[j], acc[i][j]);
        }
        if (it < 24){
            int nxt = cur^1;
            As[nxt][lk+0][lrow]=a_st.x; As[nxt][lk+1][lrow]=a_st.y;
            As[nxt][lk+2][lrow]=a_st.z; As[nxt][lk+3][lrow]=a_st.w;
            Bs[nxt][lk+0][lrow]=b_st.x; Bs[nxt][lk+1][lrow]=b_st.y;
            Bs[nxt][lk+2][lrow]=b_st.z; Bs[nxt][lk+3][lrow]=b_st.w;
            __syncthreads();
            cur = nxt;
        }
    }

    // epilogue: + colsum, rare exact correction, store
    int col0 = bn*128 + tn;
    float4 cs0 = *(const float4*)(g_colsum + col0);
    float4 cs1 = *(const float4*)(g_colsum + col0 + 32);
    const int ro[8] = {0,1,2,3,16,17,18,19};
    #pragma unroll
    for (int i=0;i<8;i++){
        int row = bm*128 + tm + ro[i];
        float4 o0, o1;
        o0.x = acc[i][0]+cs0.x; o0.y = acc[i][1]+cs0.y;
        o0.z = acc[i][2]+cs0.z; o0.w = acc[i][3]+cs0.w;
        o1.x = acc[i][4]+cs1.x; o1.y = acc[i][5]+cs1.y;
        o1.z = acc[i][6]+cs1.z; o1.w = acc[i][7]+cs1.w;
        if (g_zany[row]){   // essentially never taken; exact fallback
            float* po[8] = {&o0.x,&o0.y,&o0.z,&o0.w,&o1.x,&o1.y,&o1.z,&o1.w};
            #pragma unroll
            for (int w=0;w<7;w++){
                unsigned m = g_zmask[row][w];
                while (m){
                    int bbit = __ffs(m)-1; m &= m-1;
                    int n = w*32 + bbit;
                    #pragma unroll
                    for (int j=0;j<8;j++){
                        int col = col0 + ((j<4)? j : 28+j);
                        *po[j] -= vw[(size_t)col*FV + 2*n + 1];
                    }
                }
            }
        }
        *(float4*)(g_Y + (size_t)row*HMT + col0)      = o0;
        *(float4*)(g_Y + (size_t)row*HMT + col0 + 32) = o1;
    }
}

// ---------------------------------------------------------------------------
// K4: GRU input GEMM: GI[t,s,g] = Y[b,t,n,:] . wih[g,:] + bih[g]
// ---------------------------------------------------------------------------
__global__ void k4_gi(const float* __restrict__ wih, const float* __restrict__ bih){
    int t  = blockIdx.x / 50;
    int s0 = (blockIdx.x % 50) * 32;
    int tid = threadIdx.x;
    __shared__ __align__(16) float xsh[32*32];
    for (int idx = tid; idx < 1024; idx += 192){
        int sL = idx >> 5, i = idx & 31;
        int s = s0 + sL;
        int b = s / NNODE, n = s % NNODE;
        xsh[idx] = g_Y[((size_t)(b*TT + t)*NNODE + n)*HID + i];
    }
    __syncthreads();
    int g = tid % 96;
    int half = tid / 96;
    float4 w4[8];
    #pragma unroll
    for (int i4=0;i4<8;i4++) w4[i4] = *(const float4*)(wih + g*32 + i4*4);
    float bg = bih[g];
    for (int sL = half*16; sL < half*16+16; sL++){
        const float4* xr = (const float4*)&xsh[sL*32];
        float acc = bg;
        #pragma unroll
        for (int i4=0;i4<8;i4++){
            float4 xv = xr[i4];
            acc = fmaf(w4[i4].x, xv.x, acc);
            acc = fmaf(w4[i4].y, xv.y, acc);
            acc = fmaf(w4[i4].z, xv.z, acc);
            acc = fmaf(w4[i4].w, xv.w, acc);
        }
        g_GI[((size_t)t*NSEQ + s0 + sL)*96 + g] = acc;
    }
}

// ---------------------------------------------------------------------------
// K5: GRU recurrence (warp = sequence) + fused MLP decoder.
// ---------------------------------------------------------------------------
__global__ void __launch_bounds__(256)
k5_gru(const float* __restrict__ whh, const float* __restrict__ bhh,
       const float* __restrict__ mlp_w, const float* __restrict__ mlp_b,
       const float* __restrict__ out_w, const float* __restrict__ out_b,
       float* __restrict__ out){
    int wid = threadIdx.x >> 5;
    int j   = threadIdx.x & 31;
    int seq = blockIdx.x*8 + wid;
    int b = seq / NNODE, n = seq % NNODE;

    float wr[32], wz[32], wn[32];
    #pragma unroll
    for (int i=0;i<32;i++){
        wr[i] = whh[j*32+i];
        wz[i] = whh[(32+j)*32+i];
        wn[i] = whh[(64+j)*32+i];
    }
    float bhr = bhh[j], bhz = bhh[32+j], bhn = bhh[64+j];
    const float* gi = g_GI + (size_t)seq*96;

    float h = 0.f;
    for (int t=0;t<TT;t++){
        float hr=0.f, hz=0.f, hn=0.f;
        #pragma unroll
        for (int i=0;i<32;i++){
            float hv = __shfl_sync(0xffffffffu, h, i);
            hr = fmaf(wr[i], hv, hr);
            hz = fmaf(wz[i], hv, hz);
            hn = fmaf(wn[i], hv, hn);
        }
        const float* gt = gi + (size_t)t*(NSEQ*96);
        float r  = sigf(gt[j]    + hr + bhr);
        float z  = sigf(gt[32+j] + hz + bhz);
        float nn = ftanh(gt[64+j] + r*(hn + bhn));
        h = (1.f - z)*nn + z*h;
    }

    float h2 = mlp_b[j];
    #pragma unroll
    for (int i=0;i<32;i++)
        h2 = fmaf(mlp_w[j*32+i], __shfl_sync(0xffffffffu, h, i), h2);
    h2 = fmaxf(h2, 0.f);

    float y = (j < HOR) ? out_b[j] : 0.f;
    #pragma unroll
    for (int i=0;i<32;i++){
        float v = __shfl_sync(0xffffffffu, h2, i);
        if (j < HOR) y = fmaf(out_w[j*32+i], v, y);
    }
    if (j < HOR) out[((size_t)b*HOR + j)*NNODE + n] = y;
}

// ---------------------------------------------------------------------------
extern "C" void kernel_launch(void* const* d_in, const int* in_sizes, int n_in,
                              void* d_out, int out_size){
    const float* x    = (const float*)d_in[0];
    const float* mask = (const float*)d_in[2];
    const float* ts   = (const float*)d_in[3];
    const float* te_w = (const float*)d_in[4];
    const float* te_b = (const float*)d_in[5];
    const float* q_w  = (const float*)d_in[6];
    const float* q_b  = (const float*)d_in[7];
    const float* k_w  = (const float*)d_in[8];
    const float* v_w  = (const float*)d_in[9];
    const float* v_b  = (const float*)d_in[10];
    const float* wih  = (const float*)d_in[11];
    const float* whh  = (const float*)d_in[12];
    const float* bih  = (const float*)d_in[13];
    const float* bhh  = (const float*)d_in[14];
    const float* mlpw = (const float*)d_in[15];
    const float* mlpb = (const float*)d_in[16];
    const float* outw = (const float*)d_in[17];
    const float* outb = (const float*)d_in[18];
    float* out = (float*)d_out;

    k2b_pack<<<800, 256>>>(v_w, v_b);
    k0_qk<<<ROWS, 32>>>(ts, te_w, te_b, q_w, q_b, k_w);
    k1_scores<<<ROWS, 96>>>();
    k2_att<<<ROWS, 256>>>(x, mask);
    k3_vgemm<<<dim3(HMT/128, ROWS/128), 256>>>(v_w);
    k4_gi<<<TT*50, 192>>>(wih, bih);
    k5_gru<<<NSEQ/8, 256>>>(whh, bhh, mlpw, mlpb, outw, outb, out);
}